// round 1
// baseline (speedup 1.0000x reference)
#include <cuda_runtime.h>
#include <math.h>

#define BB 4
#define CC 256
#define NN 4096
#define CR 32

// Scratch (allocation-free rule: __device__ globals)
__device__ float g_qk[(size_t)BB * NN * 64];   // [b][n][0:32]=q, [32:64]=k   (4 MB)
__device__ float g_v [(size_t)BB * NN * CC];   // [b][m][c]                   (16 MB)

// ---------------------------------------------------------------------------
// Projection GEMM: y[b, n, o0+o] = sum_c W[o, c] * x[b, c, n]
// Tile: 64 n x 64 o per block, 256 threads, 4x4 microtile per thread.
// ---------------------------------------------------------------------------
template<bool QK>
__global__ __launch_bounds__(256) void proj_kernel(
    const float* __restrict__ x,
    const float* __restrict__ W0,
    const float* __restrict__ W1,
    float* __restrict__ out, int ldo)
{
    const int b  = blockIdx.z;
    const int n0 = blockIdx.x * 64;
    const int o0 = blockIdx.y * 64;
    const int tid = threadIdx.x;
    const int tx = tid & 15;   // n group (4 each)
    const int ty = tid >> 4;   // o group (4 each)

    __shared__ float xs[16][64];
    __shared__ float ws[64][17];

    float acc[4][4];
#pragma unroll
    for (int i = 0; i < 4; i++)
#pragma unroll
        for (int j = 0; j < 4; j++) acc[i][j] = 0.f;

    const float* xb = x + (size_t)b * CC * NN;

    for (int c0 = 0; c0 < CC; c0 += 16) {
        // stage x tile [16 c][64 n] — coalesced (64-float rows)
#pragma unroll
        for (int i = 0; i < 4; i++) {
            int e  = tid + i * 256;
            int cc = e >> 6, nn = e & 63;
            xs[cc][nn] = xb[(size_t)(c0 + cc) * NN + n0 + nn];
        }
        // stage W tile [64 o][16 c]
#pragma unroll
        for (int i = 0; i < 4; i++) {
            int e  = tid + i * 256;
            int o  = e >> 4, cc = e & 15;
            int og = o0 + o;
            float wv;
            if (QK) wv = (og < 32) ? W0[og * CC + c0 + cc]
                                   : W1[(og - 32) * CC + c0 + cc];
            else    wv = W0[og * CC + c0 + cc];
            ws[o][cc] = wv;
        }
        __syncthreads();
#pragma unroll
        for (int cc = 0; cc < 16; cc++) {
            float a[4], w[4];
#pragma unroll
            for (int i = 0; i < 4; i++) a[i] = xs[cc][tx * 4 + i];
#pragma unroll
            for (int j = 0; j < 4; j++) w[j] = ws[ty * 4 + j][cc];
#pragma unroll
            for (int i = 0; i < 4; i++)
#pragma unroll
                for (int j = 0; j < 4; j++) acc[i][j] = fmaf(a[i], w[j], acc[i][j]);
        }
        __syncthreads();
    }

#pragma unroll
    for (int i = 0; i < 4; i++) {
        int n = n0 + tx * 4 + i;
#pragma unroll
        for (int j = 0; j < 4; j++) {
            int o = o0 + ty * 4 + j;
            out[((size_t)b * NN + n) * ldo + o] = acc[i][j];
        }
    }
}

// ---------------------------------------------------------------------------
// Fused flash attention + residual.
// Block: 64 queries of one batch. 256 threads: qi = tid & 63, g = tid >> 6.
// Thread (qi, g) accumulates channels [g*64, g*64+64) for query qi.
// ---------------------------------------------------------------------------
__global__ __launch_bounds__(256, 2) void attn_kernel(
    const float* __restrict__ x, float* __restrict__ out)
{
    extern __shared__ float sm[];
    float* qs = sm;                  // [64][33]
    float* ks = qs + 64 * 33;        // [64][33]
    float* ss = ks + 64 * 33;        // [64][65]
    float* vs = ss + 64 * 65;        // [64][256]

    const int b   = blockIdx.z;
    const int n0  = blockIdx.x * 64;
    const int tid = threadIdx.x;
    const int qi  = tid & 63;
    const int g   = tid >> 6;

    // stage Q tile once
#pragma unroll
    for (int i = 0; i < 8; i++) {
        int e = tid + i * 256;
        int q = e >> 5, d = e & 31;
        qs[q * 33 + d] = g_qk[((size_t)b * NN + n0 + q) * 64 + d];
    }

    float4 acc[16];
#pragma unroll
    for (int i = 0; i < 16; i++) acc[i] = make_float4(0.f, 0.f, 0.f, 0.f);
    float mrun = -1e30f, lrun = 0.f;

    for (int m0 = 0; m0 < NN; m0 += 64) {
        __syncthreads();   // previous tile fully consumed (also covers first-iter qs)
        // stage K tile [64 j][32 d]
#pragma unroll
        for (int i = 0; i < 8; i++) {
            int e = tid + i * 256;
            int j = e >> 5, d = e & 31;
            ks[j * 33 + d] = g_qk[((size_t)b * NN + m0 + j) * 64 + 32 + d];
        }
        // stage V tile [64 j][256 c] — vectorized, coalesced
        {
            const float4* vsrc = (const float4*)(g_v + ((size_t)b * NN + m0) * CC);
            float4* vdst = (float4*)vs;
#pragma unroll
            for (int i = 0; i < 16; i++) vdst[tid + i * 256] = vsrc[tid + i * 256];
        }
        __syncthreads();

        // S tile: thread computes s[qi][j] for its 16 j's
#pragma unroll
        for (int jj = 0; jj < 16; jj++) {
            int j = g * 16 + jj;
            float s = 0.f;
#pragma unroll
            for (int d = 0; d < 32; d++)
                s = fmaf(qs[qi * 33 + d], ks[j * 33 + d], s);
            ss[qi * 65 + j] = s;
        }
        __syncthreads();

        // online softmax update
        float tmax = -1e30f;
#pragma unroll
        for (int j = 0; j < 64; j++) tmax = fmaxf(tmax, ss[qi * 65 + j]);
        float mn   = fmaxf(mrun, tmax);
        float corr = __expf(mrun - mn);
        lrun *= corr;
#pragma unroll
        for (int i = 0; i < 16; i++) {
            acc[i].x *= corr; acc[i].y *= corr;
            acc[i].z *= corr; acc[i].w *= corr;
        }
        for (int j = 0; j < 64; j++) {
            float p = __expf(ss[qi * 65 + j] - mn);
            lrun += p;
            const float4* vr = (const float4*)(vs + j * 256 + g * 64);
#pragma unroll
            for (int i = 0; i < 16; i++) {
                float4 vv = vr[i];
                acc[i].x = fmaf(p, vv.x, acc[i].x);
                acc[i].y = fmaf(p, vv.y, acc[i].y);
                acc[i].z = fmaf(p, vv.z, acc[i].z);
                acc[i].w = fmaf(p, vv.w, acc[i].w);
            }
        }
        mrun = mn;
    }

    // epilogue: out[b, c, n] = acc/l + x[b, c, n]   (coalesced over qi)
    const float inv = 1.f / lrun;
    const int n = n0 + qi;
#pragma unroll
    for (int i = 0; i < 16; i++) {
        int c = g * 64 + i * 4;
        size_t base = ((size_t)b * CC + c) * NN + n;
        out[base + 0 * NN] = acc[i].x * inv + x[base + 0 * NN];
        out[base + 1 * NN] = acc[i].y * inv + x[base + 1 * NN];
        out[base + 2 * NN] = acc[i].z * inv + x[base + 2 * NN];
        out[base + 3 * NN] = acc[i].w * inv + x[base + 3 * NN];
    }
}

// ---------------------------------------------------------------------------
extern "C" void kernel_launch(void* const* d_in, const int* in_sizes, int n_in,
                              void* d_out, int out_size)
{
    const float* x  = (const float*)d_in[0];
    const float* Wq = (const float*)d_in[1];
    const float* Wk = (const float*)d_in[2];
    const float* Wv = (const float*)d_in[3];
    float* out = (float*)d_out;

    float* qk_ptr = nullptr;
    float* v_ptr  = nullptr;
    cudaGetSymbolAddress((void**)&qk_ptr, g_qk);
    cudaGetSymbolAddress((void**)&v_ptr,  g_v);

    static const size_t attn_smem =
        (size_t)(64 * 33 + 64 * 33 + 64 * 65 + 64 * 256) * sizeof(float); // 99072 B
    cudaFuncSetAttribute(attn_kernel,
                         cudaFuncAttributeMaxDynamicSharedMemorySize,
                         (int)attn_smem);

    proj_kernel<true ><<<dim3(NN / 64, 1, BB), 256>>>(x, Wq, Wk, qk_ptr, 64);
    proj_kernel<false><<<dim3(NN / 64, CC / 64, BB), 256>>>(x, Wv, nullptr, v_ptr, CC);
    attn_kernel<<<dim3(NN / 64, 1, BB), 256, attn_smem>>>(x, out);
}

// round 2
// speedup vs baseline: 1.0400x; 1.0400x over previous
#include <cuda_runtime.h>
#include <math.h>

#define BB 4
#define CC 256
#define NN 4096
#define CR 32

typedef unsigned long long ull;

// Scratch (allocation-free rule: __device__ globals)
__device__ float g_qk[(size_t)BB * NN * 64];   // [b][n][0:32]=q, [32:64]=k   (4 MB)
__device__ float g_v [(size_t)BB * NN * CC];   // [b][m][c]                   (16 MB)

// ---------------- packed fp32x2 helpers (Blackwell) ----------------
__device__ __forceinline__ ull ffma2(ull a, ull b, ull c) {
    ull d;
    asm("fma.rn.f32x2 %0, %1, %2, %3;" : "=l"(d) : "l"(a), "l"(b), "l"(c));
    return d;
}
__device__ __forceinline__ ull fmul2(ull a, ull b) {
    ull d;
    asm("mul.rn.f32x2 %0, %1, %2;" : "=l"(d) : "l"(a), "l"(b));
    return d;
}
__device__ __forceinline__ ull pack2(float lo, float hi) {
    ull r;
    asm("mov.b64 %0, {%1, %2};" : "=l"(r) : "f"(lo), "f"(hi));
    return r;
}
__device__ __forceinline__ void unpack2(ull v, float& lo, float& hi) {
    asm("mov.b64 {%0, %1}, %2;" : "=f"(lo), "=f"(hi) : "l"(v));
}

// ---------------------------------------------------------------------------
// Projection GEMM: y[b, n, o0+o] = sum_c W[o, c] * x[b, c, n]
// Tile: 64 n x 64 o per block, 256 threads, 4x4 microtile per thread.
// ---------------------------------------------------------------------------
template<bool QK>
__global__ __launch_bounds__(256) void proj_kernel(
    const float* __restrict__ x,
    const float* __restrict__ W0,
    const float* __restrict__ W1,
    float* __restrict__ out, int ldo)
{
    const int b  = blockIdx.z;
    const int n0 = blockIdx.x * 64;
    const int o0 = blockIdx.y * 64;
    const int tid = threadIdx.x;
    const int tx = tid & 15;   // n group (4 each)
    const int ty = tid >> 4;   // o group (4 each)

    __shared__ float xs[16][64];
    __shared__ float ws[64][17];

    float acc[4][4];
#pragma unroll
    for (int i = 0; i < 4; i++)
#pragma unroll
        for (int j = 0; j < 4; j++) acc[i][j] = 0.f;

    const float* xb = x + (size_t)b * CC * NN;

    for (int c0 = 0; c0 < CC; c0 += 16) {
#pragma unroll
        for (int i = 0; i < 4; i++) {
            int e  = tid + i * 256;
            int cc = e >> 6, nn = e & 63;
            xs[cc][nn] = xb[(size_t)(c0 + cc) * NN + n0 + nn];
        }
#pragma unroll
        for (int i = 0; i < 4; i++) {
            int e  = tid + i * 256;
            int o  = e >> 4, cc = e & 15;
            int og = o0 + o;
            float wv;
            if (QK) wv = (og < 32) ? W0[og * CC + c0 + cc]
                                   : W1[(og - 32) * CC + c0 + cc];
            else    wv = W0[og * CC + c0 + cc];
            ws[o][cc] = wv;
        }
        __syncthreads();
#pragma unroll
        for (int cc = 0; cc < 16; cc++) {
            float a[4], w[4];
#pragma unroll
            for (int i = 0; i < 4; i++) a[i] = xs[cc][tx * 4 + i];
#pragma unroll
            for (int j = 0; j < 4; j++) w[j] = ws[ty * 4 + j][cc];
#pragma unroll
            for (int i = 0; i < 4; i++)
#pragma unroll
                for (int j = 0; j < 4; j++) acc[i][j] = fmaf(a[i], w[j], acc[i][j]);
        }
        __syncthreads();
    }

#pragma unroll
    for (int i = 0; i < 4; i++) {
        int n = n0 + tx * 4 + i;
#pragma unroll
        for (int j = 0; j < 4; j++) {
            int o = o0 + ty * 4 + j;
            out[((size_t)b * NN + n) * ldo + o] = acc[i][j];
        }
    }
}

// ---------------------------------------------------------------------------
// Fused flash attention + residual, f32x2-packed.
// Block: 64 queries of one batch. 256 threads: qi = tid & 63, g = tid >> 6.
// Thread (qi, g) accumulates channels [g*64, g*64+64) for query qi
// in 32 packed f32x2 accumulators. Q row lives in 16 packed registers.
// ---------------------------------------------------------------------------
__global__ __launch_bounds__(256, 2) void attn_kernel(
    const float* __restrict__ x, float* __restrict__ out)
{
    extern __shared__ float sm[];
    float* ks  = sm;                  // [64][32]   8 KB (rows 128B, broadcast reads)
    float* ss  = ks + 64 * 32;        // [64][65]   16.25 KB
    float* pms = ss + 64 * 65;        // [4][64]    1 KB partial maxima
    float* vs  = pms + 4 * 64;        // [64][256]  64 KB

    const int b   = blockIdx.z;
    const int n0  = blockIdx.x * 64;
    const int tid = threadIdx.x;
    const int qi  = tid & 63;
    const int g   = tid >> 6;

    // Q row -> registers (packed pairs over d)
    ull q2[16];
    {
        const ulonglong2* qsrc =
            (const ulonglong2*)(g_qk + ((size_t)b * NN + n0 + qi) * 64);
#pragma unroll
        for (int i = 0; i < 8; i++) {
            ulonglong2 qv = qsrc[i];
            q2[2 * i]     = qv.x;
            q2[2 * i + 1] = qv.y;
        }
    }

    ull acc2[32];
#pragma unroll
    for (int i = 0; i < 32; i++) acc2[i] = 0ULL;
    float mrun = -1e30f, lrun = 0.f;

    for (int m0 = 0; m0 < NN; m0 += 64) {
        __syncthreads();   // previous tile's PV fully consumed

        // stage K tile [64 j][32 d] (float4 granularity, coalesced+conflict-free)
        {
            const float* kbase = g_qk + ((size_t)b * NN + m0) * 64 + 32;
#pragma unroll
            for (int i = 0; i < 2; i++) {
                int e = tid + i * 256;           // e in [0,512): j = e>>3, d4 = e&7
                int j = e >> 3, d4 = e & 7;
                float4 kv = *(const float4*)(kbase + (size_t)j * 64 + d4 * 4);
                *(float4*)(ks + j * 32 + d4 * 4) = kv;
            }
        }
        // stage V tile [64 j][256 c]
        {
            const float4* vsrc = (const float4*)(g_v + ((size_t)b * NN + m0) * CC);
            float4* vdst = (float4*)vs;
#pragma unroll
            for (int i = 0; i < 16; i++) vdst[tid + i * 256] = vsrc[tid + i * 256];
        }
        __syncthreads();

        // S tile: thread computes s[qi][j] for its 16 j's (packed dot products)
        float pmax = -1e30f;
#pragma unroll
        for (int jj = 0; jj < 16; jj++) {
            int j = g * 16 + jj;
            const ulonglong2* kr = (const ulonglong2*)(ks + j * 32);
            ull s2 = 0ULL;
#pragma unroll
            for (int i = 0; i < 8; i++) {
                ulonglong2 kv = kr[i];                 // broadcast within warp
                s2 = ffma2(q2[2 * i],     kv.x, s2);
                s2 = ffma2(q2[2 * i + 1], kv.y, s2);
            }
            float slo, shi;
            unpack2(s2, slo, shi);
            float s = slo + shi;
            ss[qi * 65 + j] = s;
            pmax = fmaxf(pmax, s);
        }
        pms[g * 64 + qi] = pmax;
        __syncthreads();

        // tile max for this row from the 4 partials
        float tmax = fmaxf(fmaxf(pms[qi], pms[64 + qi]),
                           fmaxf(pms[128 + qi], pms[192 + qi]));
        float mn   = fmaxf(mrun, tmax);
        float corr = __expf(mrun - mn);
        lrun *= corr;
        {
            ull c2 = pack2(corr, corr);
#pragma unroll
            for (int i = 0; i < 32; i++) acc2[i] = fmul2(acc2[i], c2);
        }

        // PV accumulate
#pragma unroll 4
        for (int j = 0; j < 64; j++) {
            float p = __expf(ss[qi * 65 + j] - mn);
            lrun += p;
            ull p2 = pack2(p, p);
            const ulonglong2* vr = (const ulonglong2*)(vs + j * 256 + g * 64);
#pragma unroll
            for (int i = 0; i < 16; i++) {
                ulonglong2 vv = vr[i];                 // broadcast within warp
                acc2[2 * i]     = ffma2(p2, vv.x, acc2[2 * i]);
                acc2[2 * i + 1] = ffma2(p2, vv.y, acc2[2 * i + 1]);
            }
        }
        mrun = mn;
    }

    // epilogue: out[b, c, n] = acc/l + x[b, c, n]   (coalesced over qi)
    const float inv = 1.f / lrun;
    const int n = n0 + qi;
#pragma unroll
    for (int ii = 0; ii < 32; ii++) {
        int c = g * 64 + ii * 2;
        float lo, hi;
        unpack2(acc2[ii], lo, hi);
        size_t base = ((size_t)b * CC + c) * NN + n;
        out[base]      = lo * inv + x[base];
        out[base + NN] = hi * inv + x[base + NN];
    }
}

// ---------------------------------------------------------------------------
extern "C" void kernel_launch(void* const* d_in, const int* in_sizes, int n_in,
                              void* d_out, int out_size)
{
    const float* x  = (const float*)d_in[0];
    const float* Wq = (const float*)d_in[1];
    const float* Wk = (const float*)d_in[2];
    const float* Wv = (const float*)d_in[3];
    float* out = (float*)d_out;

    float* qk_ptr = nullptr;
    float* v_ptr  = nullptr;
    cudaGetSymbolAddress((void**)&qk_ptr, g_qk);
    cudaGetSymbolAddress((void**)&v_ptr,  g_v);

    static const size_t attn_smem =
        (size_t)(64 * 32 + 64 * 65 + 4 * 64 + 64 * 256) * sizeof(float); // 91392 B
    cudaFuncSetAttribute(attn_kernel,
                         cudaFuncAttributeMaxDynamicSharedMemorySize,
                         (int)attn_smem);

    proj_kernel<true ><<<dim3(NN / 64, 1, BB), 256>>>(x, Wq, Wk, qk_ptr, 64);
    proj_kernel<false><<<dim3(NN / 64, CC / 64, BB), 256>>>(x, Wv, nullptr, v_ptr, CC);
    attn_kernel<<<dim3(NN / 64, 1, BB), 256, attn_smem>>>(x, out);
}